// round 6
// baseline (speedup 1.0000x reference)
#include <cuda_runtime.h>
#include <cstdint>

// AUGRU, B=2048, T=200, D=H=64.
//  K1 (pre): Y1 = x@Wgx + gb [BT,128], Y2 = x@Wcx + cb [BT,64]  (unchanged R5)
//  K2 (rec): M=5 rows/CTA, 128 threads, grid 410, 3 CTAs/SM.
//            gate NT=8/ks=8, cand NT=4/ks=8, f32x2 throughout.

#define B_ 2048
#define T_ 200
#define D_ 64
#define H_ 64

typedef unsigned long long ull;

__device__ float Y1g[B_ * T_ * 128];
__device__ float Y2g[B_ * T_ * 64];

__device__ __forceinline__ ull pack2(float lo, float hi) {
    ull r; asm("mov.b64 %0, {%1, %2};" : "=l"(r) : "f"(lo), "f"(hi)); return r;
}
__device__ __forceinline__ void unpack2(ull v, float& lo, float& hi) {
    asm("mov.b64 {%0, %1}, %2;" : "=f"(lo), "=f"(hi) : "l"(v));
}
__device__ __forceinline__ ull ffma2(ull a, ull b, ull c) {
    ull d; asm("fma.rn.f32x2 %0, %1, %2, %3;" : "=l"(d) : "l"(a), "l"(b), "l"(c)); return d;
}
__device__ __forceinline__ ull add2(ull a, ull b) {
    ull d; asm("add.rn.f32x2 %0, %1, %2;" : "=l"(d) : "l"(a), "l"(b)); return d;
}
__device__ __forceinline__ float hadd2(ull v) {
    float lo, hi; unpack2(v, lo, hi); return lo + hi;
}
__device__ __forceinline__ float sigmoid_f(float x) {
    return __fdividef(1.0f, 1.0f + __expf(-x));
}
__device__ __forceinline__ float tanh_f(float x) {
    float e = __expf(2.0f * x);
    return 1.0f - __fdividef(2.0f, e + 1.0f);
}
__device__ __forceinline__ void cpa16(void* s, const void* g) {
    uint32_t sa = (uint32_t)__cvta_generic_to_shared(s);
    asm volatile("cp.async.ca.shared.global [%0], [%1], 16;" :: "r"(sa), "l"(g));
}
__device__ __forceinline__ void cpa4(void* s, const void* g) {
    uint32_t sa = (uint32_t)__cvta_generic_to_shared(s);
    asm volatile("cp.async.ca.shared.global [%0], [%1], 4;" :: "r"(sa), "l"(g));
}

// ============================ K1: precompute (unchanged) =====================
#define PT 256
#define PGRID 296
#define NTILES ((B_ * T_) / 64)   // 6400

struct PSmem {
    float w[64][192];
    float sx[2][64][64];
};
#define PSMEM_BYTES ((int)sizeof(PSmem))

__global__ __launch_bounds__(PT, 2)
void pre_kernel(const float* __restrict__ x,
                const float* __restrict__ gk,
                const float* __restrict__ gb,
                const float* __restrict__ ck,
                const float* __restrict__ cb)
{
    extern __shared__ char praw[];
    PSmem* S = reinterpret_cast<PSmem*>(praw);
    const int tid = threadIdx.x;
    const int cg  = tid & 31;
    const int rg  = tid >> 5;

    for (int idx = tid; idx < 64 * 48; idx += PT) {
        int k = idx / 48, c4 = idx % 48;
        float4 v;
        if (c4 < 32) v = ((const float4*)(gk + k * 128))[c4];
        else         v = ((const float4*)(ck + k * 64))[c4 - 32];
        ((float4*)&S->w[k][0])[c4] = v;
    }
    ull bias[3];
#pragma unroll
    for (int j = 0; j < 3; j++) {
        int c = 64 * j + 2 * cg;
        float lo = (c < 128) ? gb[c] : cb[c - 128];
        float hi = (c < 128) ? gb[c + 1] : cb[c + 1 - 128];
        bias[j] = pack2(lo, hi);
    }

    int tile = blockIdx.x;
    auto prefetch = [&](int tl, int bb) {
        const char* src = (const char*)(x + (size_t)tl * 64 * 64);
        char* dst = (char*)&S->sx[bb][0][0];
#pragma unroll
        for (int i = 0; i < 4; i++)
            cpa16(dst + tid * 16 + i * 4096, src + tid * 16 + i * 4096);
        asm volatile("cp.async.commit_group;");
    };
    prefetch(tile, 0);
    int buf = 0;

    for (; tile < NTILES; tile += PGRID) {
        int nt = tile + PGRID;
        if (nt < NTILES) prefetch(nt, buf ^ 1);
        else asm volatile("cp.async.commit_group;");
        asm volatile("cp.async.wait_group 1;");
        __syncthreads();

        ull acc[8][3];
#pragma unroll
        for (int r = 0; r < 8; r++)
#pragma unroll
            for (int j = 0; j < 3; j++) acc[r][j] = bias[j];

        const float* xs = &S->sx[buf][rg * 8][0];
#pragma unroll 4
        for (int kk = 0; kk < 16; kk++) {
            ull bx[4][3];
#pragma unroll
            for (int ks = 0; ks < 4; ks++)
#pragma unroll
                for (int j = 0; j < 3; j++)
                    bx[ks][j] = *(const ull*)&S->w[kk * 4 + ks][64 * j + 2 * cg];
#pragma unroll
            for (int r = 0; r < 8; r++) {
                float4 a = *(const float4*)(xs + r * 64 + kk * 4);
                ull a0 = pack2(a.x, a.x), a1 = pack2(a.y, a.y);
                ull a2 = pack2(a.z, a.z), a3 = pack2(a.w, a.w);
#pragma unroll
                for (int j = 0; j < 3; j++) {
                    acc[r][j] = ffma2(bx[0][j], a0, acc[r][j]);
                    acc[r][j] = ffma2(bx[1][j], a1, acc[r][j]);
                    acc[r][j] = ffma2(bx[2][j], a2, acc[r][j]);
                    acc[r][j] = ffma2(bx[3][j], a3, acc[r][j]);
                }
            }
        }

#pragma unroll
        for (int r = 0; r < 8; r++) {
            int row = tile * 64 + rg * 8 + r;
            float lo, hi;
            unpack2(acc[r][0], lo, hi);
            *(float2*)&Y1g[row * 128 + 2 * cg]      = make_float2(lo, hi);
            unpack2(acc[r][1], lo, hi);
            *(float2*)&Y1g[row * 128 + 64 + 2 * cg] = make_float2(lo, hi);
            unpack2(acc[r][2], lo, hi);
            *(float2*)&Y2g[row * 64 + 2 * cg]       = make_float2(lo, hi);
        }
        __syncthreads();
        buf ^= 1;
    }
}

// ============================ K2: recurrence ================================
#define M_ 5
#define RTHREADS 128
#define NCTA_R ((B_ + M_ - 1) / M_)   // 410

struct RSmem {
    float sy1[2][M_][128];
    float sy2[2][M_][64];
    float sh[M_][64];
    float srh[M_][64];
    float su[M_][64];
    float ps[8 * M_ * 128];   // gate [8][5][128]; cand reuses prefix [8][5][64]
    float sa[2][8];
    int   sl[8];
};
#define RSMEM_BYTES ((int)sizeof(RSmem))

__global__ __launch_bounds__(RTHREADS, 3)
void augru_rec(const int*   __restrict__ slen_g,
               const float* __restrict__ att,   // [B,T]
               const float* __restrict__ gk,
               const float* __restrict__ ck,
               float*       __restrict__ out)
{
    extern __shared__ char smem_raw[];
    RSmem* S = reinterpret_cast<RSmem*>(smem_raw);

    const int tid = threadIdx.x;
    const int b0  = blockIdx.x * M_;

    // gate: 16 col-groups (NT=8: cols 8g..8g+7) x 8 k-slices (8k = 4 kp)
    const int gcg = tid & 15;
    const int gks = tid >> 4;
    // cand: 16 col-groups (NT=4: cols 4g..4g+3) x 8 k-slices (8k = 4 kp)
    const int ccg = tid & 15;
    const int cks = tid >> 4;

    ull wg2[4][8];
#pragma unroll
    for (int kp = 0; kp < 4; kp++) {
        int k = 64 + gks * 8 + 2 * kp;
#pragma unroll
        for (int c = 0; c < 8; c++)
            wg2[kp][c] = pack2(gk[k * 128 + 8 * gcg + c],
                               gk[(k + 1) * 128 + 8 * gcg + c]);
    }
    ull wc2[4][4];
#pragma unroll
    for (int kp = 0; kp < 4; kp++) {
        int k = 64 + cks * 8 + 2 * kp;
#pragma unroll
        for (int c = 0; c < 4; c++)
            wc2[kp][c] = pack2(ck[k * 64 + 4 * ccg + c],
                               ck[(k + 1) * 64 + 4 * ccg + c]);
    }

    for (int idx = tid; idx < M_ * 64; idx += RTHREADS)
        (&S->sh[0][0])[idx] = 0.0f;
    if (tid < M_) {
        int b = b0 + tid; if (b >= B_) b = B_ - 1;
        S->sl[tid] = slen_g[b];
    }

    // prefetch roles (sy1: 160 float4, sy2: 80 float4)
    auto clampb = [&](int m) { int b = b0 + m; return (b < B_) ? b : B_ - 1; };
    const int b1a = clampb(tid >> 5);            // sy1 i = tid
    const int b1b = clampb((tid + 128) >> 5);    // sy1 i = tid+128 (tid<32)
    const int b2a = clampb(tid >> 4);            // sy2 i = tid (tid<80)
    const int ba  = clampb(tid);                 // sa  (tid<M_)

    auto do_prefetch = [&](int tt, int bb) {
        {
            int q = tid & 31;
            cpa16((char*)&S->sy1[bb][0][0] + tid * 16,
                  &Y1g[(b1a * T_ + tt) * 128 + q * 4]);
        }
        if (tid < 32) {
            int i = tid + 128, q = i & 31;
            cpa16((char*)&S->sy1[bb][0][0] + i * 16,
                  &Y1g[(b1b * T_ + tt) * 128 + q * 4]);
        }
        if (tid < 80) {
            int q = tid & 15;
            cpa16((char*)&S->sy2[bb][0][0] + tid * 16,
                  &Y2g[(b2a * T_ + tt) * 64 + q * 4]);
        }
        if (tid < M_)
            cpa4(&S->sa[bb][tid], &att[ba * T_ + tt]);
        asm volatile("cp.async.commit_group;");
    };

    do_prefetch(0, 0);
    asm volatile("cp.async.wait_group 0;");
    __syncthreads();

    for (int t = 0; t < T_; ++t) {
        const int buf  = t & 1;
        const int nbuf = buf ^ 1;
        do_prefetch((t + 1 < T_) ? t + 1 : t, nbuf);

        // ---- Phase A: gate h-GEMM partials (NT=8, 4 kp per thread)
#pragma unroll
        for (int m = 0; m < M_; m++) {
            const ulonglong2* p = (const ulonglong2*)&S->sh[m][gks * 8];
            ulonglong2 v0 = p[0], v1 = p[1];
            ull acc[8];
#pragma unroll
            for (int c = 0; c < 8; c++) {
                acc[c] = ffma2(wg2[0][c], v0.x, 0ull);
                acc[c] = ffma2(wg2[1][c], v0.y, acc[c]);
                acc[c] = ffma2(wg2[2][c], v1.x, acc[c]);
                acc[c] = ffma2(wg2[3][c], v1.y, acc[c]);
            }
            float* dst = &S->ps[(gks * M_ + m) * 128 + 8 * gcg];
            *(float4*)dst =
                make_float4(hadd2(acc[0]), hadd2(acc[1]), hadd2(acc[2]), hadd2(acc[3]));
            *(float4*)(dst + 4) =
                make_float4(hadd2(acc[4]), hadd2(acc[5]), hadd2(acc[6]), hadd2(acc[7]));
        }
        __syncthreads();

        // ---- Phase B: gate finalize (8 packed adds, sigmoid -> srh/su)
#pragma unroll
        for (int it = 0; it < 3; it++) {
            int p = tid + it * 128;
            if (p < M_ * 64) {
                int m = p >> 6, n0 = (p & 63) * 2;
                ull s = *(const ull*)&S->sy1[buf][m][n0];
#pragma unroll
                for (int k2 = 0; k2 < 8; k2++)
                    s = add2(s, *(const ull*)&S->ps[(k2 * M_ + m) * 128 + n0]);
                float g0, g1; unpack2(s, g0, g1);
                g0 = sigmoid_f(g0); g1 = sigmoid_f(g1);
                if (n0 < 64) {
                    float2 hv = *(const float2*)&S->sh[m][n0];
                    *(float2*)&S->srh[m][n0] = make_float2(g0 * hv.x, g1 * hv.y);
                } else {
                    *(float2*)&S->su[m][n0 - 64] = make_float2(g0, g1);
                }
            }
        }
        __syncthreads();

        // ---- Phase C: cand rh-GEMM partials (NT=4, 4 kp per thread)
#pragma unroll
        for (int m = 0; m < M_; m++) {
            const ulonglong2* p = (const ulonglong2*)&S->srh[m][cks * 8];
            ulonglong2 v0 = p[0], v1 = p[1];
            ull acc[4];
#pragma unroll
            for (int c = 0; c < 4; c++) {
                acc[c] = ffma2(wc2[0][c], v0.x, 0ull);
                acc[c] = ffma2(wc2[1][c], v0.y, acc[c]);
                acc[c] = ffma2(wc2[2][c], v1.x, acc[c]);
                acc[c] = ffma2(wc2[3][c], v1.y, acc[c]);
            }
            *(float4*)&S->ps[(cks * M_ + m) * 64 + 4 * ccg] =
                make_float4(hadd2(acc[0]), hadd2(acc[1]), hadd2(acc[2]), hadd2(acc[3]));
        }
        __syncthreads();

        // ---- Phase D: cand finalize + h update + output
#pragma unroll
        for (int it = 0; it < 2; it++) {
            int p = tid + it * 128;
            if (p < M_ * 32) {
                int m = p >> 5, n0 = (p & 31) * 2;
                ull s = *(const ull*)&S->sy2[buf][m][n0];
#pragma unroll
                for (int k2 = 0; k2 < 8; k2++)
                    s = add2(s, *(const ull*)&S->ps[(k2 * M_ + m) * 64 + n0]);
                float c0, c1; unpack2(s, c0, c1);
                c0 = tanh_f(c0); c1 = tanh_f(c1);
                float2 uv = *(const float2*)&S->su[m][n0];
                float2 hv = *(const float2*)&S->sh[m][n0];
                float a   = S->sa[buf][m];
                float uh0 = (1.0f - a) * uv.x;
                float uh1 = (1.0f - a) * uv.y;
                float hn0 = uh0 * hv.x + (1.0f - uh0) * c0;
                float hn1 = uh1 * hv.y + (1.0f - uh1) * c1;
                bool valid = (t < S->sl[m]);
                *(float2*)&S->sh[m][n0] =
                    make_float2(valid ? hn0 : hv.x, valid ? hn1 : hv.y);
                int b = b0 + m;
                if (b < B_)
                    *(float2*)&out[(b * T_ + t) * 64 + n0] =
                        make_float2(valid ? hn0 : 0.0f, valid ? hn1 : 0.0f);
            }
        }
        asm volatile("cp.async.wait_group 0;");
        __syncthreads();
    }
}

extern "C" void kernel_launch(void* const* d_in, const int* in_sizes, int n_in,
                              void* d_out, int out_size) {
    const float* x   = (const float*)d_in[0];
    const int*   sl  = (const int*)  d_in[1];
    const float* att = (const float*)d_in[2];
    const float* gk  = (const float*)d_in[3];
    const float* gb  = (const float*)d_in[4];
    const float* ck  = (const float*)d_in[5];
    const float* cb  = (const float*)d_in[6];
    float* out = (float*)d_out;

    cudaFuncSetAttribute(pre_kernel,
                         cudaFuncAttributeMaxDynamicSharedMemorySize, PSMEM_BYTES);
    pre_kernel<<<PGRID, PT, PSMEM_BYTES>>>(x, gk, gb, ck, cb);

    cudaFuncSetAttribute(augru_rec,
                         cudaFuncAttributeMaxDynamicSharedMemorySize, RSMEM_BYTES);
    augru_rec<<<NCTA_R, RTHREADS, RSMEM_BYTES>>>(sl, att, gk, ck, out);
}

// round 7
// speedup vs baseline: 1.1250x; 1.1250x over previous
#include <cuda_runtime.h>
#include <cstdint>

// AUGRU, B=2048, T=200, D=H=64.
//  K1 (pre): Y1 = x@Wgx + gb [BT,128], Y2 = x@Wcx + cb [BT,64]  (R5, proven)
//  K2 (rec): R5 skeleton (M=7, 256 thr, 2 CTAs/SM, NT=2 tilings) +
//            r-only phase B (u folded into phase D) + depth-2 cp.async.

#define B_ 2048
#define T_ 200
#define D_ 64
#define H_ 64

typedef unsigned long long ull;

__device__ float Y1g[B_ * T_ * 128];
__device__ float Y2g[B_ * T_ * 64];

__device__ __forceinline__ ull pack2(float lo, float hi) {
    ull r; asm("mov.b64 %0, {%1, %2};" : "=l"(r) : "f"(lo), "f"(hi)); return r;
}
__device__ __forceinline__ void unpack2(ull v, float& lo, float& hi) {
    asm("mov.b64 {%0, %1}, %2;" : "=f"(lo), "=f"(hi) : "l"(v));
}
__device__ __forceinline__ ull ffma2(ull a, ull b, ull c) {
    ull d; asm("fma.rn.f32x2 %0, %1, %2, %3;" : "=l"(d) : "l"(a), "l"(b), "l"(c)); return d;
}
__device__ __forceinline__ ull add2(ull a, ull b) {
    ull d; asm("add.rn.f32x2 %0, %1, %2;" : "=l"(d) : "l"(a), "l"(b)); return d;
}
__device__ __forceinline__ float hadd2(ull v) {
    float lo, hi; unpack2(v, lo, hi); return lo + hi;
}
__device__ __forceinline__ float sigmoid_f(float x) {
    return __fdividef(1.0f, 1.0f + __expf(-x));
}
__device__ __forceinline__ float tanh_f(float x) {
    float e = __expf(2.0f * x);
    return 1.0f - __fdividef(2.0f, e + 1.0f);
}
__device__ __forceinline__ void cpa16(void* s, const void* g) {
    uint32_t sa = (uint32_t)__cvta_generic_to_shared(s);
    asm volatile("cp.async.ca.shared.global [%0], [%1], 16;" :: "r"(sa), "l"(g));
}
__device__ __forceinline__ void cpa4(void* s, const void* g) {
    uint32_t sa = (uint32_t)__cvta_generic_to_shared(s);
    asm volatile("cp.async.ca.shared.global [%0], [%1], 4;" :: "r"(sa), "l"(g));
}

// ============================ K1: precompute (R5, unchanged) =================
#define PT 256
#define PGRID 296
#define NTILES ((B_ * T_) / 64)   // 6400

struct PSmem {
    float w[64][192];
    float sx[2][64][64];
};
#define PSMEM_BYTES ((int)sizeof(PSmem))

__global__ __launch_bounds__(PT, 2)
void pre_kernel(const float* __restrict__ x,
                const float* __restrict__ gk,
                const float* __restrict__ gb,
                const float* __restrict__ ck,
                const float* __restrict__ cb)
{
    extern __shared__ char praw[];
    PSmem* S = reinterpret_cast<PSmem*>(praw);
    const int tid = threadIdx.x;
    const int cg  = tid & 31;
    const int rg  = tid >> 5;

    for (int idx = tid; idx < 64 * 48; idx += PT) {
        int k = idx / 48, c4 = idx % 48;
        float4 v;
        if (c4 < 32) v = ((const float4*)(gk + k * 128))[c4];
        else         v = ((const float4*)(ck + k * 64))[c4 - 32];
        ((float4*)&S->w[k][0])[c4] = v;
    }
    ull bias[3];
#pragma unroll
    for (int j = 0; j < 3; j++) {
        int c = 64 * j + 2 * cg;
        float lo = (c < 128) ? gb[c] : cb[c - 128];
        float hi = (c < 128) ? gb[c + 1] : cb[c + 1 - 128];
        bias[j] = pack2(lo, hi);
    }

    int tile = blockIdx.x;
    auto prefetch = [&](int tl, int bb) {
        const char* src = (const char*)(x + (size_t)tl * 64 * 64);
        char* dst = (char*)&S->sx[bb][0][0];
#pragma unroll
        for (int i = 0; i < 4; i++)
            cpa16(dst + tid * 16 + i * 4096, src + tid * 16 + i * 4096);
        asm volatile("cp.async.commit_group;");
    };
    prefetch(tile, 0);
    int buf = 0;

    for (; tile < NTILES; tile += PGRID) {
        int nt = tile + PGRID;
        if (nt < NTILES) prefetch(nt, buf ^ 1);
        else asm volatile("cp.async.commit_group;");
        asm volatile("cp.async.wait_group 1;");
        __syncthreads();

        ull acc[8][3];
#pragma unroll
        for (int r = 0; r < 8; r++)
#pragma unroll
            for (int j = 0; j < 3; j++) acc[r][j] = bias[j];

        const float* xs = &S->sx[buf][rg * 8][0];
#pragma unroll 4
        for (int kk = 0; kk < 16; kk++) {
            ull bx[4][3];
#pragma unroll
            for (int ks = 0; ks < 4; ks++)
#pragma unroll
                for (int j = 0; j < 3; j++)
                    bx[ks][j] = *(const ull*)&S->w[kk * 4 + ks][64 * j + 2 * cg];
#pragma unroll
            for (int r = 0; r < 8; r++) {
                float4 a = *(const float4*)(xs + r * 64 + kk * 4);
                ull a0 = pack2(a.x, a.x), a1 = pack2(a.y, a.y);
                ull a2 = pack2(a.z, a.z), a3 = pack2(a.w, a.w);
#pragma unroll
                for (int j = 0; j < 3; j++) {
                    acc[r][j] = ffma2(bx[0][j], a0, acc[r][j]);
                    acc[r][j] = ffma2(bx[1][j], a1, acc[r][j]);
                    acc[r][j] = ffma2(bx[2][j], a2, acc[r][j]);
                    acc[r][j] = ffma2(bx[3][j], a3, acc[r][j]);
                }
            }
        }

#pragma unroll
        for (int r = 0; r < 8; r++) {
            int row = tile * 64 + rg * 8 + r;
            float lo, hi;
            unpack2(acc[r][0], lo, hi);
            *(float2*)&Y1g[row * 128 + 2 * cg]      = make_float2(lo, hi);
            unpack2(acc[r][1], lo, hi);
            *(float2*)&Y1g[row * 128 + 64 + 2 * cg] = make_float2(lo, hi);
            unpack2(acc[r][2], lo, hi);
            *(float2*)&Y2g[row * 64 + 2 * cg]       = make_float2(lo, hi);
        }
        __syncthreads();
        buf ^= 1;
    }
}

// ============================ K2: recurrence ================================
#define M_ 7
#define RTHREADS 256
#define NCTA_R ((B_ + M_ - 1) / M_)   // 293

struct RSmem {
    float sy1[3][M_][128];   // triple buffer (depth-2 pipeline)
    float sy2[3][M_][64];
    float sh[M_][64];
    float srh[M_][64];
    float psg[4 * M_ * 128]; // gate partials — persist through phase C
    float psc[8 * M_ * 64];  // cand partials
    float sa[3][8];
    int   sl[8];
};
#define RSMEM_BYTES ((int)sizeof(RSmem))

__global__ __launch_bounds__(RTHREADS, 2)
void augru_rec(const int*   __restrict__ slen_g,
               const float* __restrict__ att,   // [B,T]
               const float* __restrict__ gk,
               const float* __restrict__ ck,
               float*       __restrict__ out)
{
    extern __shared__ char smem_raw[];
    RSmem* S = reinterpret_cast<RSmem*>(smem_raw);

    const int tid = threadIdx.x;
    const int b0  = blockIdx.x * M_;

    // gate: 64 col-pairs (NT=2) x 4 k-slices (16 k = 8 kp)
    const int gng = tid & 63;
    const int gks = tid >> 6;
    // cand: 32 col-pairs (NT=2) x 8 k-slices (8 k = 4 kp)
    const int cng = tid & 31;
    const int cks = tid >> 5;

    ull wg2[8][2];
#pragma unroll
    for (int kp = 0; kp < 8; kp++) {
        int k = 64 + gks * 16 + 2 * kp;
#pragma unroll
        for (int c = 0; c < 2; c++)
            wg2[kp][c] = pack2(gk[k * 128 + 2 * gng + c],
                               gk[(k + 1) * 128 + 2 * gng + c]);
    }
    ull wc2[4][2];
#pragma unroll
    for (int kp = 0; kp < 4; kp++) {
        int k = 64 + cks * 8 + 2 * kp;
#pragma unroll
        for (int c = 0; c < 2; c++)
            wc2[kp][c] = pack2(ck[k * 64 + 2 * cng + c],
                               ck[(k + 1) * 64 + 2 * cng + c]);
    }

    for (int idx = tid; idx < M_ * 64; idx += RTHREADS)
        (&S->sh[0][0])[idx] = 0.0f;
    if (tid < M_) {
        int b = b0 + tid; if (b >= B_) b = B_ - 1;
        S->sl[tid] = slen_g[b];
    }

    const int y1m = tid >> 5, y1q = tid & 31;
    const int y2m = tid >> 4, y2q = tid & 15;
    int by1 = b0 + y1m; if (by1 >= B_) by1 = B_ - 1;
    int by2 = b0 + y2m; if (by2 >= B_) by2 = B_ - 1;
    int ba  = b0 + tid; if (ba  >= B_) ba  = B_ - 1;

    auto do_prefetch = [&](int tt, int bb) {
        if (tid < 224)
            cpa16((char*)&S->sy1[bb][0][0] + tid * 16,
                  &Y1g[(by1 * T_ + tt) * 128 + y1q * 4]);
        if (tid < 112)
            cpa16((char*)&S->sy2[bb][0][0] + tid * 16,
                  &Y2g[(by2 * T_ + tt) * 64 + y2q * 4]);
        if (tid < M_)
            cpa4(&S->sa[bb][tid], &att[ba * T_ + tt]);
        asm volatile("cp.async.commit_group;");
    };

    // depth-2 pipeline: P(0), P(1) in flight; wait until P(0) done
    do_prefetch(0, 0);
    do_prefetch(1 < T_ ? 1 : 0, 1);
    asm volatile("cp.async.wait_group 1;");
    __syncthreads();

    for (int t = 0; t < T_; ++t) {
        const int buf = t % 3;
        {
            int tn = (t + 2 < T_) ? t + 2 : T_ - 1;
            do_prefetch(tn, (t + 2) % 3);   // buffer (t+2)%3 free since step t-1
        }

        // ---- Phase A: gate h-GEMM partials (k-pair FFMA2, 2 cols) -> psg
#pragma unroll
        for (int mh = 0; mh < 2; mh++) {
            const int mbase = mh * 4;
            const int mcnt  = mh ? 3 : 4;
            ull acc[4][2];
#pragma unroll
            for (int mm = 0; mm < 4; mm++)
                { acc[mm][0] = 0ull; acc[mm][1] = 0ull; }
#pragma unroll
            for (int mm = 0; mm < 4; mm++) {
                if (mm >= mcnt) break;
                const ulonglong2* p =
                    (const ulonglong2*)&S->sh[mbase + mm][gks * 16];
                ulonglong2 v0 = p[0], v1 = p[1], v2 = p[2], v3 = p[3];
#pragma unroll
                for (int c = 0; c < 2; c++) {
                    acc[mm][c] = ffma2(wg2[0][c], v0.x, acc[mm][c]);
                    acc[mm][c] = ffma2(wg2[1][c], v0.y, acc[mm][c]);
                    acc[mm][c] = ffma2(wg2[2][c], v1.x, acc[mm][c]);
                    acc[mm][c] = ffma2(wg2[3][c], v1.y, acc[mm][c]);
                    acc[mm][c] = ffma2(wg2[4][c], v2.x, acc[mm][c]);
                    acc[mm][c] = ffma2(wg2[5][c], v2.y, acc[mm][c]);
                    acc[mm][c] = ffma2(wg2[6][c], v3.x, acc[mm][c]);
                    acc[mm][c] = ffma2(wg2[7][c], v3.y, acc[mm][c]);
                }
            }
#pragma unroll
            for (int mm = 0; mm < 4; mm++) {
                if (mm >= mcnt) break;
                *(float2*)&S->psg[(gks * M_ + mbase + mm) * 128 + 2 * gng] =
                    make_float2(hadd2(acc[mm][0]), hadd2(acc[mm][1]));
            }
        }
        __syncthreads();

        // ---- Phase B: r-gate finalize ONLY (224 items) -> srh
        if (tid < M_ * 32) {
            int m = tid >> 5, n0 = (tid & 31) * 2;    // n0 in [0,62]
            ull s = *(const ull*)&S->sy1[buf][m][n0];
#pragma unroll
            for (int k2 = 0; k2 < 4; k2++)
                s = add2(s, *(const ull*)&S->psg[(k2 * M_ + m) * 128 + n0]);
            float g0, g1; unpack2(s, g0, g1);
            g0 = sigmoid_f(g0); g1 = sigmoid_f(g1);
            float2 hv = *(const float2*)&S->sh[m][n0];
            *(float2*)&S->srh[m][n0] = make_float2(g0 * hv.x, g1 * hv.y);
        }
        __syncthreads();

        // ---- Phase C: cand rh-GEMM partials -> psc
#pragma unroll
        for (int mh = 0; mh < 2; mh++) {
            const int mbase = mh * 4;
            const int mcnt  = mh ? 3 : 4;
            ull acc[4][2];
#pragma unroll
            for (int mm = 0; mm < 4; mm++)
                { acc[mm][0] = 0ull; acc[mm][1] = 0ull; }
#pragma unroll
            for (int mm = 0; mm < 4; mm++) {
                if (mm >= mcnt) break;
                const ulonglong2* p =
                    (const ulonglong2*)&S->srh[mbase + mm][cks * 8];
                ulonglong2 v0 = p[0], v1 = p[1];
#pragma unroll
                for (int c = 0; c < 2; c++) {
                    acc[mm][c] = ffma2(wc2[0][c], v0.x, acc[mm][c]);
                    acc[mm][c] = ffma2(wc2[1][c], v0.y, acc[mm][c]);
                    acc[mm][c] = ffma2(wc2[2][c], v1.x, acc[mm][c]);
                    acc[mm][c] = ffma2(wc2[3][c], v1.y, acc[mm][c]);
                }
            }
#pragma unroll
            for (int mm = 0; mm < 4; mm++) {
                if (mm >= mcnt) break;
                *(float2*)&S->psc[(cks * M_ + mbase + mm) * 64 + 2 * cng] =
                    make_float2(hadd2(acc[mm][0]), hadd2(acc[mm][1]));
            }
        }
        __syncthreads();

        // ---- Phase D: u-gate finalize + cand finalize + h update + output
        if (tid < M_ * 32) {
            int m = tid >> 5, n0 = (tid & 31) * 2;    // n0 in [0,62]
            // u-gate: cols 64+n0, 64+n0+1
            ull su_ = *(const ull*)&S->sy1[buf][m][64 + n0];
#pragma unroll
            for (int k2 = 0; k2 < 4; k2++)
                su_ = add2(su_, *(const ull*)&S->psg[(k2 * M_ + m) * 128 + 64 + n0]);
            float u0, u1; unpack2(su_, u0, u1);
            u0 = sigmoid_f(u0); u1 = sigmoid_f(u1);
            // candidate
            ull sc_ = *(const ull*)&S->sy2[buf][m][n0];
#pragma unroll
            for (int k2 = 0; k2 < 8; k2++)
                sc_ = add2(sc_, *(const ull*)&S->psc[(k2 * M_ + m) * 64 + n0]);
            float c0, c1; unpack2(sc_, c0, c1);
            c0 = tanh_f(c0); c1 = tanh_f(c1);
            // update
            float2 hv = *(const float2*)&S->sh[m][n0];
            float a   = S->sa[buf][m];
            float uh0 = (1.0f - a) * u0;
            float uh1 = (1.0f - a) * u1;
            float hn0 = uh0 * hv.x + (1.0f - uh0) * c0;
            float hn1 = uh1 * hv.y + (1.0f - uh1) * c1;
            bool valid = (t < S->sl[m]);
            *(float2*)&S->sh[m][n0] =
                make_float2(valid ? hn0 : hv.x, valid ? hn1 : hv.y);
            int b = b0 + m;
            if (b < B_)
                *(float2*)&out[(b * T_ + t) * 64 + n0] =
                    make_float2(valid ? hn0 : 0.0f, valid ? hn1 : 0.0f);
        }
        asm volatile("cp.async.wait_group 1;");   // ensure P(t+1) landed
        __syncthreads();
    }
    asm volatile("cp.async.wait_group 0;");       // drain before exit
}

extern "C" void kernel_launch(void* const* d_in, const int* in_sizes, int n_in,
                              void* d_out, int out_size) {
    const float* x   = (const float*)d_in[0];
    const int*   sl  = (const int*)  d_in[1];
    const float* att = (const float*)d_in[2];
    const float* gk  = (const float*)d_in[3];
    const float* gb  = (const float*)d_in[4];
    const float* ck  = (const float*)d_in[5];
    const float* cb  = (const float*)d_in[6];
    float* out = (float*)d_out;

    cudaFuncSetAttribute(pre_kernel,
                         cudaFuncAttributeMaxDynamicSharedMemorySize, PSMEM_BYTES);
    pre_kernel<<<PGRID, PT, PSMEM_BYTES>>>(x, gk, gb, ck, cb);

    cudaFuncSetAttribute(augru_rec,
                         cudaFuncAttributeMaxDynamicSharedMemorySize, RSMEM_BYTES);
    augru_rec<<<NCTA_R, RTHREADS, RSMEM_BYTES>>>(sl, att, gk, ck, out);
}